// round 4
// baseline (speedup 1.0000x reference)
#include <cuda_runtime.h>

#define NNODES 50000
#define NHEADS 8
#define EPS 1e-8f
#define ATT_NORM 2.0f
#define UNROLL 4

// Scratch: per-(node, head) running max of nj, stored as float (compared via
// int bits — valid because all values are >= 0 and the init value is 0.0f).
__device__ float g_node_max[NNODES * NHEADS];

// Warp-per-edge layout: warp w owns edge e. The 32 lanes cooperatively load
// the 32 float4s (= 8 heads x 16 dims) of that edge with ONE coalesced
// warp-wide LDG.128 (512B contiguous). Lane group (lane>>2) = head h,
// sub-lane (lane&3) = dim quarter. Sum-of-squares reduced across the 4-lane
// group via shfl_xor; lane&3==0 finishes sqrt + scatter-atomicMax.
__global__ void scatter_max_kernel(const float4* __restrict__ x_j,
                                   const int* __restrict__ index,
                                   int E) {
    int lane = threadIdx.x & 31;
    int warp = (blockIdx.x * blockDim.x + threadIdx.x) >> 5;
    int nwarps = (gridDim.x * blockDim.x) >> 5;
    int h = lane >> 2;

    for (int e0 = warp * UNROLL; e0 < E; e0 += nwarps * UNROLL) {
        int m = E - e0; if (m > UNROLL) m = UNROLL;
        float4 v[UNROLL];
        int nd[UNROLL];
#pragma unroll
        for (int k = 0; k < UNROLL; ++k)
            if (k < m) v[k] = x_j[(size_t)(e0 + k) * 32 + lane];
#pragma unroll
        for (int k = 0; k < UNROLL; ++k)
            if (k < m) nd[k] = index[e0 + k];          // broadcast load
#pragma unroll
        for (int k = 0; k < UNROLL; ++k) {
            if (k >= m) break;
            float s = v[k].x * v[k].x + v[k].y * v[k].y
                    + v[k].z * v[k].z + v[k].w * v[k].w;
            s += __shfl_xor_sync(0xFFFFFFFFu, s, 1);
            s += __shfl_xor_sync(0xFFFFFFFFu, s, 2);
            if ((lane & 3) == 0) {
                float nj = sqrtf(s) + EPS;
                int node = nd[k];
                if ((unsigned)node < NNODES)
                    atomicMax((int*)&g_node_max[node * NHEADS + h],
                              __float_as_int(nj));
            }
        }
    }
}

// Same warp-per-edge layout for the finalize pass.
__global__ void finalize_kernel(const float* __restrict__ e_ij,
                                const float4* __restrict__ x_i,
                                const int* __restrict__ index,
                                float* __restrict__ out,
                                int E) {
    int lane = threadIdx.x & 31;
    int warp = (blockIdx.x * blockDim.x + threadIdx.x) >> 5;
    int nwarps = (gridDim.x * blockDim.x) >> 5;
    int h = lane >> 2;

    for (int e0 = warp * UNROLL; e0 < E; e0 += nwarps * UNROLL) {
        int m = E - e0; if (m > UNROLL) m = UNROLL;
        float4 v[UNROLL];
        int nd[UNROLL];
#pragma unroll
        for (int k = 0; k < UNROLL; ++k)
            if (k < m) v[k] = x_i[(size_t)(e0 + k) * 32 + lane];
#pragma unroll
        for (int k = 0; k < UNROLL; ++k)
            if (k < m) nd[k] = index[e0 + k];
#pragma unroll
        for (int k = 0; k < UNROLL; ++k) {
            if (k >= m) break;
            float s = v[k].x * v[k].x + v[k].y * v[k].y
                    + v[k].z * v[k].z + v[k].w * v[k].w;
            s += __shfl_xor_sync(0xFFFFFFFFu, s, 1);
            s += __shfl_xor_sync(0xFFFFFFFFu, s, 2);
            if ((lane & 3) == 0) {
                int e = e0 + k;
                float ni = sqrtf(s) + EPS;
                int node = nd[k];
                float mx = 0.0f;
                if ((unsigned)node < NNODES)
                    mx = g_node_max[node * NHEADS + h];   // L2-resident gather
                mx += EPS;
                float denom = ATT_NORM * (ni + mx) + EPS;
                float r = e_ij[(size_t)e * NHEADS + h] / denom;
                r = fminf(10.0f, fmaxf(-10.0f, r));
                out[(size_t)e * NHEADS + h] = r;
            }
        }
    }
}

extern "C" void kernel_launch(void* const* d_in, const int* in_sizes, int n_in,
                              void* d_out, int out_size) {
    // metadata order: e_ij [E,H] f32, x_i [E,H,D] f32, x_j [E,H,D] f32, index [E] i32
    const float*  e_ij  = (const float*)d_in[0];
    const float4* x_i   = (const float4*)d_in[1];
    const float4* x_j   = (const float4*)d_in[2];
    const int*    index = (const int*)d_in[3];
    float*        out   = (float*)d_out;

    int E = in_sizes[0] / NHEADS;        // 800,000

    // Zero the scratch via a memset node (cheaper than a kernel launch).
    void* nm_ptr = nullptr;
    cudaGetSymbolAddress(&nm_ptr, g_node_max);
    cudaMemsetAsync(nm_ptr, 0, sizeof(float) * NNODES * NHEADS, 0);

    const int B = 256;                   // 8 warps/block
    int warp_tasks = (E + UNROLL - 1) / UNROLL;          // warps needed
    int blocks = (warp_tasks + (B / 32) - 1) / (B / 32); // one pass, no loop iter >1

    scatter_max_kernel<<<blocks, B>>>(x_j, index, E);
    finalize_kernel<<<blocks, B>>>(e_ij, x_i, index, out, E);
}

// round 5
// speedup vs baseline: 1.0712x; 1.0712x over previous
#include <cuda_runtime.h>

#define NNODES 50000
#define NHEADS 8
#define EPS 1e-8f
#define ATT_NORM 2.0f

// Scratch: per-(node, head) running max of nj as float bits (all values >= 0,
// init 0x00000000, so int atomicMax == float max).
__device__ float g_node_max[NNODES * NHEADS];

// Layout: warp w owns 4 consecutive edges (32 (e,h) pairs, 2KB of x data).
// Lane loads v[k] = x4[w*128 + k*32 + lane]  -> 4 perfectly-coalesced 512B LDG.128.
// After per-float4 square + shfl_xor(1) + shfl_xor(2), lane 4*s register k holds
// the full sum-of-squares of edge (base+k), head s.
__global__ void scatter_max_kernel(const float4* __restrict__ x_j,
                                   const int* __restrict__ index,
                                   int E) {
    int lane = threadIdx.x & 31;
    int w = (blockIdx.x * blockDim.x + threadIdx.x) >> 5;
    int ebase = w * 4;
    if (ebase >= E) return;

    float4 v[4];
    float sq[4];
#pragma unroll
    for (int k = 0; k < 4; ++k)
        v[k] = x_j[(size_t)w * 128 + k * 32 + lane];
#pragma unroll
    for (int k = 0; k < 4; ++k) {
        float s = v[k].x * v[k].x + v[k].y * v[k].y
                + v[k].z * v[k].z + v[k].w * v[k].w;
        s += __shfl_xor_sync(0xFFFFFFFFu, s, 1);
        s += __shfl_xor_sync(0xFFFFFFFFu, s, 2);
        sq[k] = s;
    }

    if ((lane & 3) == 0) {
        int h = lane >> 2;                       // head 0..7
#pragma unroll
        for (int k = 0; k < 4; ++k) {
            int e = ebase + k;
            if (e >= E) break;
            float nj = sqrtf(sq[k]) + EPS;
            int node = index[e];                 // broadcast across 8 lanes
            if ((unsigned)node < NNODES)
                atomicMax((int*)&g_node_max[node * NHEADS + h],
                          __float_as_int(nj));
        }
    }
}

__global__ void finalize_kernel(const float* __restrict__ e_ij,
                                const float4* __restrict__ x_i,
                                const int* __restrict__ index,
                                float* __restrict__ out,
                                int E) {
    int lane = threadIdx.x & 31;
    int w = (blockIdx.x * blockDim.x + threadIdx.x) >> 5;
    int ebase = w * 4;
    if (ebase >= E) return;

    float4 v[4];
    float sq[4];
#pragma unroll
    for (int k = 0; k < 4; ++k)
        v[k] = x_i[(size_t)w * 128 + k * 32 + lane];
#pragma unroll
    for (int k = 0; k < 4; ++k) {
        float s = v[k].x * v[k].x + v[k].y * v[k].y
                + v[k].z * v[k].z + v[k].w * v[k].w;
        s += __shfl_xor_sync(0xFFFFFFFFu, s, 1);
        s += __shfl_xor_sync(0xFFFFFFFFu, s, 2);
        sq[k] = s;
    }

    if ((lane & 3) == 0) {
        int h = lane >> 2;
#pragma unroll
        for (int k = 0; k < 4; ++k) {
            int e = ebase + k;
            if (e >= E) break;
            float ni = sqrtf(sq[k]) + EPS;
            int node = index[e];
            float mx = 0.0f;
            if ((unsigned)node < NNODES)
                mx = g_node_max[node * NHEADS + h];   // L2-resident gather
            mx += EPS;
            float denom = ATT_NORM * (ni + mx) + EPS;
            float r = e_ij[(size_t)e * NHEADS + h] / denom;
            r = fminf(10.0f, fmaxf(-10.0f, r));
            out[(size_t)e * NHEADS + h] = r;          // 8 lanes, 32B contiguous
        }
    }
}

extern "C" void kernel_launch(void* const* d_in, const int* in_sizes, int n_in,
                              void* d_out, int out_size) {
    // metadata order: e_ij [E,H] f32, x_i [E,H,D] f32, x_j [E,H,D] f32, index [E] i32
    const float*  e_ij  = (const float*)d_in[0];
    const float4* x_i   = (const float4*)d_in[1];
    const float4* x_j   = (const float4*)d_in[2];
    const int*    index = (const int*)d_in[3];
    float*        out   = (float*)d_out;

    int E = in_sizes[0] / NHEADS;        // 800,000

    // Zero the scratch via a memset node (cheaper than a kernel launch).
    void* nm_ptr = nullptr;
    cudaGetSymbolAddress(&nm_ptr, g_node_max);
    cudaMemsetAsync(nm_ptr, 0, sizeof(float) * NNODES * NHEADS, 0);

    const int B = 256;                                   // 8 warps/block
    int warps = (E + 3) / 4;                             // 4 edges per warp
    int blocks = (warps + (B / 32) - 1) / (B / 32);      // 25000

    scatter_max_kernel<<<blocks, B>>>(x_j, index, E);
    finalize_kernel<<<blocks, B>>>(e_ij, x_i, index, out, E);
}

// round 6
// speedup vs baseline: 1.1569x; 1.0800x over previous
#include <cuda_runtime.h>

#define NNODES 50000
#define NHEADS 8
#define EPS 1e-8f
#define ATT_NORM 2.0f

// Scratch: per-(node, head) running max of nj as float bits (all values >= 0,
// init 0x00000000, so int atomicMax == float max).
__device__ float g_node_max[NNODES * NHEADS];

// Warp w owns 4 consecutive edges. Lane loads v[k] = x4[w*128 + k*32 + lane]
// -> 4 perfectly-coalesced 512B warp loads. shfl_xor(1)+shfl_xor(2) completes
// the 16-dim sum-of-squares within each 4-lane group (head = lane>>2).
__global__ void scatter_max_kernel(const float4* __restrict__ x_j,
                                   const int* __restrict__ index,
                                   int E) {
    int lane = threadIdx.x & 31;
    int w = (blockIdx.x * blockDim.x + threadIdx.x) >> 5;
    int ebase = w * 4;
    if (ebase >= E) return;

    float4 v[4];
    float sq[4];
#pragma unroll
    for (int k = 0; k < 4; ++k)
        v[k] = x_j[(size_t)w * 128 + k * 32 + lane];
#pragma unroll
    for (int k = 0; k < 4; ++k) {
        float s = v[k].x * v[k].x + v[k].y * v[k].y
                + v[k].z * v[k].z + v[k].w * v[k].w;
        s += __shfl_xor_sync(0xFFFFFFFFu, s, 1);
        s += __shfl_xor_sync(0xFFFFFFFFu, s, 2);
        sq[k] = s;
    }

    // Redistribute: lane L handles edge ebase+(L>>3), head L&7.
    float bc[4];
#pragma unroll
    for (int k = 0; k < 4; ++k)
        bc[k] = __shfl_sync(0xFFFFFFFFu, sq[k], (lane & 7) * 4);
    int ksel = lane >> 3;
    float ss = (ksel == 0) ? bc[0] : (ksel == 1) ? bc[1]
             : (ksel == 2) ? bc[2] : bc[3];

    int e = ebase + ksel;
    int h = lane & 7;
    if (e < E) {
        float nj = sqrtf(ss) + EPS;
        int node = index[e];
        if ((unsigned)node < NNODES)
            atomicMax((int*)&g_node_max[node * NHEADS + h], __float_as_int(nj));
    }
}

__global__ void finalize_kernel(const float* __restrict__ e_ij,
                                const float4* __restrict__ x_i,
                                const int* __restrict__ index,
                                float* __restrict__ out,
                                int E) {
    int lane = threadIdx.x & 31;
    int w = (blockIdx.x * blockDim.x + threadIdx.x) >> 5;
    int ebase = w * 4;
    if (ebase >= E) return;

    float4 v[4];
    float sq[4];
#pragma unroll
    for (int k = 0; k < 4; ++k)
        v[k] = x_i[(size_t)w * 128 + k * 32 + lane];
#pragma unroll
    for (int k = 0; k < 4; ++k) {
        float s = v[k].x * v[k].x + v[k].y * v[k].y
                + v[k].z * v[k].z + v[k].w * v[k].w;
        s += __shfl_xor_sync(0xFFFFFFFFu, s, 1);
        s += __shfl_xor_sync(0xFFFFFFFFu, s, 2);
        sq[k] = s;
    }

    // Redistribute: lane L handles edge ebase+(L>>3), head L&7.
    float bc[4];
#pragma unroll
    for (int k = 0; k < 4; ++k)
        bc[k] = __shfl_sync(0xFFFFFFFFu, sq[k], (lane & 7) * 4);
    int ksel = lane >> 3;
    float ss = (ksel == 0) ? bc[0] : (ksel == 1) ? bc[1]
             : (ksel == 2) ? bc[2] : bc[3];

    int e = ebase + ksel;
    int h = lane & 7;
    if (e < E) {
        float ni = sqrtf(ss) + EPS;
        int node = index[e];                      // 4 distinct addrs per warp
        float mx = 0.0f;
        if ((unsigned)node < NNODES)
            mx = g_node_max[node * NHEADS + h];   // 32 parallel L2 gathers
        mx += EPS;
        float denom = ATT_NORM * (ni + mx) + EPS;
        float r = __fdividef(e_ij[(size_t)ebase * 8 + lane], denom);  // coalesced
        r = fminf(10.0f, fmaxf(-10.0f, r));
        out[(size_t)ebase * 8 + lane] = r;        // coalesced 128B STG
    }
}

extern "C" void kernel_launch(void* const* d_in, const int* in_sizes, int n_in,
                              void* d_out, int out_size) {
    // metadata order: e_ij [E,H] f32, x_i [E,H,D] f32, x_j [E,H,D] f32, index [E] i32
    const float*  e_ij  = (const float*)d_in[0];
    const float4* x_i   = (const float4*)d_in[1];
    const float4* x_j   = (const float4*)d_in[2];
    const int*    index = (const int*)d_in[3];
    float*        out   = (float*)d_out;

    int E = in_sizes[0] / NHEADS;        // 800,000

    void* nm_ptr = nullptr;
    cudaGetSymbolAddress(&nm_ptr, g_node_max);
    cudaMemsetAsync(nm_ptr, 0, sizeof(float) * NNODES * NHEADS, 0);

    const int B = 256;                                   // 8 warps/block
    int warps = (E + 3) / 4;                             // 4 edges per warp
    int blocks = (warps + (B / 32) - 1) / (B / 32);      // 25000

    scatter_max_kernel<<<blocks, B>>>(x_j, index, E);
    finalize_kernel<<<blocks, B>>>(e_ij, x_i, index, out, E);
}

// round 11
// speedup vs baseline: 1.1900x; 1.0287x over previous
#include <cuda_runtime.h>

#define NNODES 50000
#define NHEADS 8
#define EPS 1e-8f
#define ATT_NORM 2.0f

// Scratch: per-(node, head) running max of nj as float bits (all values >= 0,
// init 0x00000000, so int atomicMax == float max).
__device__ float g_node_max[NNODES * NHEADS];

// Warp w owns 4 consecutive edges. Lane loads v[k] = x4[w*128 + k*32 + lane]
// -> perfectly-coalesced 512B warp loads. shfl_xor(1)+shfl_xor(2) completes
// the 16-dim sum-of-squares within each 4-lane group; then 4 broadcast
// shuffles give every lane exactly one (edge, head) pair.
__global__ void scatter_max_kernel(const float4* __restrict__ x_j,
                                   const int* __restrict__ index,
                                   int E) {
    int lane = threadIdx.x & 31;
    int w = (blockIdx.x * blockDim.x + threadIdx.x) >> 5;
    int ebase = w * 4;
    if (ebase >= E) return;

    float4 v[4];
    float sq[4];
#pragma unroll
    for (int k = 0; k < 4; ++k)
        v[k] = __ldcs(&x_j[(size_t)w * 128 + k * 32 + lane]);
#pragma unroll
    for (int k = 0; k < 4; ++k) {
        float s = v[k].x * v[k].x + v[k].y * v[k].y
                + v[k].z * v[k].z + v[k].w * v[k].w;
        s += __shfl_xor_sync(0xFFFFFFFFu, s, 1);
        s += __shfl_xor_sync(0xFFFFFFFFu, s, 2);
        sq[k] = s;
    }

    float bc[4];
#pragma unroll
    for (int k = 0; k < 4; ++k)
        bc[k] = __shfl_sync(0xFFFFFFFFu, sq[k], (lane & 7) * 4);
    int ksel = lane >> 3;
    float ss = (ksel == 0) ? bc[0] : (ksel == 1) ? bc[1]
             : (ksel == 2) ? bc[2] : bc[3];

    int e = ebase + ksel;
    int h = lane & 7;
    if (e < E) {
        float nj = sqrtf(ss) + EPS;
        int node = index[e];
        if ((unsigned)node < NNODES)
            atomicMax((int*)&g_node_max[node * NHEADS + h], __float_as_int(nj));
    }
}

// Finalize: warp w owns 8 consecutive edges (64 (e,h) pairs -> 2 per lane).
// All independent loads issued up front for deep MLP; x/e streams use .cs so
// g_node_max stays L2-resident for the gathers.
__global__ void __launch_bounds__(256) finalize_kernel(
        const float* __restrict__ e_ij,
        const float4* __restrict__ x_i,
        const int* __restrict__ index,
        float* __restrict__ out,
        int E) {
    int lane = threadIdx.x & 31;
    int w = (blockIdx.x * blockDim.x + threadIdx.x) >> 5;
    int ebase = w * 8;
    if (ebase >= E) return;

    int ksel = lane >> 3;
    int h = lane & 7;
    int eA = ebase + ksel;
    int eB = ebase + 4 + ksel;

    if (ebase + 8 <= E) {
        // ---- fast path: full batch, all loads front-issued ----
        float4 v[8];
#pragma unroll
        for (int k = 0; k < 8; ++k)
            v[k] = __ldcs(&x_i[(size_t)w * 256 + k * 32 + lane]);
        float evA = __ldcs(&e_ij[(size_t)ebase * 8 + lane]);
        float evB = __ldcs(&e_ij[(size_t)(ebase + 4) * 8 + lane]);
        int nodeA = index[eA];
        int nodeB = index[eB];

        float sq[8];
#pragma unroll
        for (int k = 0; k < 8; ++k) {
            float s = v[k].x * v[k].x + v[k].y * v[k].y
                    + v[k].z * v[k].z + v[k].w * v[k].w;
            s += __shfl_xor_sync(0xFFFFFFFFu, s, 1);
            s += __shfl_xor_sync(0xFFFFFFFFu, s, 2);
            sq[k] = s;
        }
        float bc[8];
#pragma unroll
        for (int k = 0; k < 8; ++k)
            bc[k] = __shfl_sync(0xFFFFFFFFu, sq[k], (lane & 7) * 4);
        float ssA = (ksel == 0) ? bc[0] : (ksel == 1) ? bc[1]
                  : (ksel == 2) ? bc[2] : bc[3];
        float ssB = (ksel == 0) ? bc[4] : (ksel == 1) ? bc[5]
                  : (ksel == 2) ? bc[6] : bc[7];

        float mxA = ((unsigned)nodeA < NNODES) ? g_node_max[nodeA * NHEADS + h] : 0.0f;
        float mxB = ((unsigned)nodeB < NNODES) ? g_node_max[nodeB * NHEADS + h] : 0.0f;

        float niA = sqrtf(ssA) + EPS;
        float dA = ATT_NORM * (niA + (mxA + EPS)) + EPS;
        float rA = __fdividef(evA, dA);
        rA = fminf(10.0f, fmaxf(-10.0f, rA));
        __stcs(&out[(size_t)ebase * 8 + lane], rA);

        float niB = sqrtf(ssB) + EPS;
        float dB = ATT_NORM * (niB + (mxB + EPS)) + EPS;
        float rB = __fdividef(evB, dB);
        rB = fminf(10.0f, fmaxf(-10.0f, rB));
        __stcs(&out[(size_t)(ebase + 4) * 8 + lane], rB);
    } else {
        // ---- tail path (E not a multiple of 8): 4-edge batches with guards ----
        for (int b = 0; b < 2; ++b) {
            int eb0 = ebase + b * 4;
            if (eb0 >= E) break;
            float4 v[4];
            float sq[4];
#pragma unroll
            for (int k = 0; k < 4; ++k) {
                int e = eb0 + k;
                v[k] = (e < E) ? x_i[(size_t)e * 32 + lane]
                               : make_float4(0.f, 0.f, 0.f, 0.f);
            }
#pragma unroll
            for (int k = 0; k < 4; ++k) {
                float s = v[k].x * v[k].x + v[k].y * v[k].y
                        + v[k].z * v[k].z + v[k].w * v[k].w;
                s += __shfl_xor_sync(0xFFFFFFFFu, s, 1);
                s += __shfl_xor_sync(0xFFFFFFFFu, s, 2);
                sq[k] = s;
            }
            float bc[4];
#pragma unroll
            for (int k = 0; k < 4; ++k)
                bc[k] = __shfl_sync(0xFFFFFFFFu, sq[k], (lane & 7) * 4);
            float ss = (ksel == 0) ? bc[0] : (ksel == 1) ? bc[1]
                     : (ksel == 2) ? bc[2] : bc[3];
            int e = eb0 + ksel;
            if (e < E) {
                float ni = sqrtf(ss) + EPS;
                int node = index[e];
                float mx = ((unsigned)node < NNODES) ? g_node_max[node * NHEADS + h] : 0.0f;
                float denom = ATT_NORM * (ni + (mx + EPS)) + EPS;
                float r = __fdividef(e_ij[(size_t)eb0 * 8 + lane], denom);
                r = fminf(10.0f, fmaxf(-10.0f, r));
                out[(size_t)eb0 * 8 + lane] = r;
            }
        }
    }
}

extern "C" void kernel_launch(void* const* d_in, const int* in_sizes, int n_in,
                              void* d_out, int out_size) {
    // metadata order: e_ij [E,H] f32, x_i [E,H,D] f32, x_j [E,H,D] f32, index [E] i32
    const float*  e_ij  = (const float*)d_in[0];
    const float4* x_i   = (const float4*)d_in[1];
    const float4* x_j   = (const float4*)d_in[2];
    const int*    index = (const int*)d_in[3];
    float*        out   = (float*)d_out;

    int E = in_sizes[0] / NHEADS;        // 800,000

    void* nm_ptr = nullptr;
    cudaGetSymbolAddress(&nm_ptr, g_node_max);
    cudaMemsetAsync(nm_ptr, 0, sizeof(float) * NNODES * NHEADS, 0);

    const int B = 256;                                   // 8 warps/block
    int warps4 = (E + 3) / 4;
    int blocks4 = (warps4 + (B / 32) - 1) / (B / 32);    // 25000
    int warps8 = (E + 7) / 8;
    int blocks8 = (warps8 + (B / 32) - 1) / (B / 32);    // 12500

    scatter_max_kernel<<<blocks4, B>>>(x_j, index, E);
    finalize_kernel<<<blocks8, B>>>(e_ij, x_i, index, out, E);
}